// round 5
// baseline (speedup 1.0000x reference)
#include <cuda_runtime.h>
#include <cstdint>

// Problem constants
#define BB   8
#define CIN  64
#define COUT 128
#define HH   224
#define WW   224
#define HW   (HH * WW)
#define PTCH 16
#define GG   14     // 14x14 patch grid
#define NP   196

typedef unsigned long long u64;
typedef unsigned int u32;

// ---------------------------------------------------------------------------
// Scratch (device globals — no allocations allowed)
// ---------------------------------------------------------------------------
__device__ u64 g_sx[BB * HW];                          // packed sign(x)
__device__ u64 g_pw[NP * 9];                           // packed sign(patch_filters)
__device__ __align__(16) int8_t g_bsa[(size_t)BB * HW * CIN];  // ternary bsa, channels-last

#define WA_STRIDE 592                                  // 576 + pad; 592B = 148 banks -> conflict-free
__device__ __align__(16) int8_t g_wA[COUT * WA_STRIDE];  // int8 weights, row o, k = t*64+h*32+kl

// ---------------------------------------------------------------------------
// Kernel 0: pack sign bits of x (4 pixels/thread, float4 loads)
// ---------------------------------------------------------------------------
__global__ void __launch_bounds__(256) pack_x_kernel(const float* __restrict__ x) {
    int q = blockIdx.x * blockDim.x + threadIdx.x;
    const int NQ = BB * HW / 4;
    if (q >= NQ) return;
    int pix = q * 4;
    int b   = pix / HW;
    int rem = pix - b * HW;
    const float4* xp = (const float4*)(x + (size_t)b * CIN * HW + rem);
    u64 w0 = 0, w1 = 0, w2 = 0, w3 = 0;
#pragma unroll
    for (int c = 0; c < CIN; c++) {
        float4 v = xp[(size_t)c * (HW / 4)];
        w0 |= (u64)(__float_as_uint(v.x) >> 31) << c;
        w1 |= (u64)(__float_as_uint(v.y) >> 31) << c;
        w2 |= (u64)(__float_as_uint(v.z) >> 31) << c;
        w3 |= (u64)(__float_as_uint(v.w) >> 31) << c;
    }
    g_sx[pix + 0] = w0;
    g_sx[pix + 1] = w1;
    g_sx[pix + 2] = w2;
    g_sx[pix + 3] = w3;
}

// ---------------------------------------------------------------------------
// Kernel 0b: pack patch-filter sign bits (for stage1)
// ---------------------------------------------------------------------------
__global__ void pack_pf_kernel(const float* __restrict__ pf) {
    int i = blockIdx.x * blockDim.x + threadIdx.x;
    if (i >= NP * 9) return;
    int p = i / 9, t = i - p * 9;
    u64 w = 0;
#pragma unroll
    for (int c = 0; c < CIN; c++) {
        unsigned sb = __float_as_uint(pf[((size_t)c * NP + p) * 9 + t]) >> 31;
        w |= (u64)sb << c;
    }
    g_pw[i] = w;
}

// ---------------------------------------------------------------------------
// Kernel 0c: pack output-conv weights as int8 rows wA[o][kg], kg = t*64 + c.
// ---------------------------------------------------------------------------
__global__ void pack_wA_kernel(const float* __restrict__ of) {
    int idx = blockIdx.x * blockDim.x + threadIdx.x;
    if (idx >= COUT * WA_STRIDE) return;
    int o = idx / WA_STRIDE, kg = idx - o * WA_STRIDE;
    int8_t v = 0;
    if (kg < 576) {
        int t = kg >> 6, c = kg & 63;
        unsigned sb = __float_as_uint(of[((size_t)o * CIN + c) * 9 + t]) >> 31;
        v = sb ? (int8_t)-1 : (int8_t)1;
    }
    g_wA[idx] = v;
}

// ---------------------------------------------------------------------------
// Kernel 1: per-patch depthwise binary 3x3 conv -> ternary bsa as int8.
// ---------------------------------------------------------------------------
__global__ void __launch_bounds__(256) stage1_kernel() {
    __shared__ u64 tile[PTCH][PTCH];
    __shared__ u64 pw9[9];

    const int gx = blockIdx.x, gy = blockIdx.y, b = blockIdx.z;
    const int j = threadIdx.x, i = threadIdx.y;
    const int tid = i * PTCH + j;
    const int patch = gy * GG + gx;

    const int y = gy * PTCH + i;
    const int x = gx * PTCH + j;
    const int pixbase = b * HW;

    tile[i][j] = g_sx[pixbase + y * WW + x];
    if (tid < 9) pw9[tid] = g_pw[patch * 9 + tid];
    __syncthreads();

    u64 c0 = 0, c1 = 0, c2 = 0, c3 = 0;
#pragma unroll
    for (int di = 0; di < 3; di++) {
#pragma unroll
        for (int dj = 0; dj < 3; dj++) {
            int li = i + di - 1, lj = j + dj - 1;
            if (li >= 0 && li < PTCH && lj >= 0 && lj < PTCH) {
                u64 d = tile[li][lj] ^ pw9[di * 3 + dj];
                u64 carry = d, u;
                u = c0 & carry; c0 ^= carry; carry = u;
                u = c1 & carry; c1 ^= carry; carry = u;
                u = c2 & carry; c2 ^= carry; carry = u;
                c3 ^= carry;
            }
        }
    }

    const int ni = (i == 0 || i == PTCH - 1) ? 2 : 3;
    const int nj = (j == 0 || j == PTCH - 1) ? 2 : 3;
    const int n  = ni * nj;

    u64 m, s;
    if (n == 9) {
        m = ~0ULL;
        s = c3 | (c2 & (c1 | c0));
    } else if (n == 6) {
        m = ~(c0 & c1 & ~c2);
        s = c2;
    } else { // n == 4
        m = ~(c1 & ~c0 & ~c2);
        s = (c0 & c1) | c2;
    }

    // Emit ternary int8: m ? (s ? -1 : +1) : 0, channels-last.
    u32 w32[16];
#pragma unroll
    for (int wi = 0; wi < 16; wi++) {
        u32 v = 0;
#pragma unroll
        for (int bi = 0; bi < 4; bi++) {
            int c = wi * 4 + bi;
            u32 mb = (u32)((m >> c) & 1ULL);
            u32 sb = (u32)((s >> c) & 1ULL);
            u32 byte = mb ? (sb ? 0xFFu : 0x01u) : 0u;
            v |= byte << (bi * 8);
        }
        w32[wi] = v;
    }
    uint4* dst = (uint4*)(g_bsa + ((size_t)(pixbase + y * WW + x)) * CIN);
    dst[0] = make_uint4(w32[0],  w32[1],  w32[2],  w32[3]);
    dst[1] = make_uint4(w32[4],  w32[5],  w32[6],  w32[7]);
    dst[2] = make_uint4(w32[8],  w32[9],  w32[10], w32[11]);
    dst[3] = make_uint4(w32[12], w32[13], w32[14], w32[15]);
}

// ---------------------------------------------------------------------------
// Kernel 2: final conv as int8 implicit GEMM via mma.sync + ldmatrix.
//   M = COUT (128 = 8 m16), N = 256 pixels (16x16 tile = 32 n8), K = 576.
//   Block: 256 threads = 2 M-warps x 4 N-warps; warp tile 4 m16 x 8 n8.
//   All fragments loaded via LDSM (x4): 6 load instrs / warp / K-step.
// ---------------------------------------------------------------------------
#define HALO_STRIDE 80
#define SMEM_A_BYTES (COUT * WA_STRIDE)          // 75776
#define SMEM_HALO_BYTES (18 * 18 * HALO_STRIDE)  // 25920
#define SMEM_TOTAL (SMEM_A_BYTES + SMEM_HALO_BYTES)

__device__ __forceinline__ void mma_s8(int* d, const u32* a, const u32* b) {
    asm volatile(
        "mma.sync.aligned.m16n8k32.row.col.s32.s8.s8.s32 "
        "{%0,%1,%2,%3}, {%4,%5,%6,%7}, {%8,%9}, {%0,%1,%2,%3};\n"
        : "+r"(d[0]), "+r"(d[1]), "+r"(d[2]), "+r"(d[3])
        : "r"(a[0]), "r"(a[1]), "r"(a[2]), "r"(a[3]),
          "r"(b[0]), "r"(b[1]));
}

__device__ __forceinline__ void ldsm_x4(u32 addr, u32& r0, u32& r1, u32& r2, u32& r3) {
    asm volatile(
        "ldmatrix.sync.aligned.m8n8.x4.shared.b16 {%0,%1,%2,%3}, [%4];"
        : "=r"(r0), "=r"(r1), "=r"(r2), "=r"(r3) : "r"(addr));
}

__global__ void __launch_bounds__(256, 1) stage2_kernel(float* __restrict__ out) {
    extern __shared__ char sm[];
    const u32 smb = (u32)__cvta_generic_to_shared(sm);

    const int tid = threadIdx.x;
    const int b  = blockIdx.z;
    const int x0 = blockIdx.x * 16, y0 = blockIdx.y * 16;

    // Load weights into smem
    {
        const uint4* src = (const uint4*)g_wA;
        uint4* dst = (uint4*)sm;
        for (int i = tid; i < SMEM_A_BYTES / 16; i += 256) dst[i] = src[i];
    }
    // Load 18x18 pixel halo of bsa (64 B each), zero-padded at image edges
    for (int idx = tid; idx < 324; idx += 256) {
        int hy = idx / 18, hx = idx - hy * 18;
        int gy = y0 - 1 + hy, gx = x0 - 1 + hx;
        uint4 v0 = make_uint4(0, 0, 0, 0), v1 = v0, v2 = v0, v3 = v0;
        if (gy >= 0 && gy < HH && gx >= 0 && gx < WW) {
            const uint4* s = (const uint4*)(g_bsa + ((size_t)((b * HH + gy) * WW + gx)) * CIN);
            v0 = s[0]; v1 = s[1]; v2 = s[2]; v3 = s[3];
        }
        uint4* d = (uint4*)(sm + SMEM_A_BYTES + (hy * 18 + hx) * HALO_STRIDE);
        d[0] = v0; d[1] = v1; d[2] = v2; d[3] = v3;
    }
    __syncthreads();

    const int warp = tid >> 5, lane = tid & 31;
    const int wm = warp & 1, wn = warp >> 1;       // 2 M-warps x 4 N-warps
    const int gid = lane >> 2, tig = lane & 3;
    const int o_base = wm * 64;

    // LDSM lane-address setup.
    // A mtile i (16 o-rows x 32B k-chunk as 4 8x16B mats):
    //   lanes 0-15 -> rows (lane&15), k-seg 0; lanes 16-31 -> same rows, k-seg 16.
    u32 aaddr[4];
#pragma unroll
    for (int i = 0; i < 4; i++)
        aaddr[i] = smb + (u32)((o_base + i * 16 + (lane & 15)) * WA_STRIDE
                               + ((lane >> 4) << 4));

    // B pair jp covers ntiles (2jp, 2jp+1): same ty, tx8 = 0 / 8.
    //   lanes 0-7: pixels x 0-7 seg0; 8-15: seg16; 16-23: x 8-15 seg0; 24-31: seg16.
    u32 baddr[4];
    int pty[4];
#pragma unroll
    for (int jp = 0; jp < 4; jp++) {
        int ty = wn * 4 + jp;
        pty[jp] = ty;
        baddr[jp] = smb + SMEM_A_BYTES
                  + (u32)((ty * 18 + ((lane >> 4) << 3) + (lane & 7)) * HALO_STRIDE
                          + ((lane >> 3) & 1) * 16);
    }

    int acc[4][8][4];
#pragma unroll
    for (int i = 0; i < 4; i++)
#pragma unroll
        for (int j = 0; j < 8; j++)
#pragma unroll
            for (int k = 0; k < 4; k++) acc[i][j][k] = 0;

    // K loop: ks -> (tap t = ks>>1, half h = ks&1). All offsets constant-folded.
#pragma unroll
    for (int ks = 0; ks < 18; ks++) {
        const int t = ks >> 1, h = ks & 1;
        const int dy = t / 3, dx = t - dy * 3;
        const u32 bofs = (u32)((dy * 18 + dx) * HALO_STRIDE + h * 32);
        const u32 aofs = (u32)(ks * 32);

        u32 a[4][4];
#pragma unroll
        for (int i = 0; i < 4; i++)
            ldsm_x4(aaddr[i] + aofs, a[i][0], a[i][1], a[i][2], a[i][3]);

        u32 bb[4][4];   // bb[jp][0..1] = ntile 2jp; [2..3] = ntile 2jp+1
#pragma unroll
        for (int jp = 0; jp < 4; jp++)
            ldsm_x4(baddr[jp] + bofs, bb[jp][0], bb[jp][1], bb[jp][2], bb[jp][3]);

#pragma unroll
        for (int i = 0; i < 4; i++)
#pragma unroll
            for (int j = 0; j < 8; j++)
                mma_s8(acc[i][j], a[i], &bb[j >> 1][(j & 1) * 2]);
    }

    // Epilogue: C frag row = o, col = pixel x -> coalesced float2 stores.
#pragma unroll
    for (int i = 0; i < 4; i++) {
        int o = o_base + i * 16 + gid;
#pragma unroll
        for (int j = 0; j < 8; j++) {
            int gy = y0 + pty[j >> 1];
            int gx = x0 + (j & 1) * 8 + tig * 2;
            size_t base0 = ((size_t)(b * COUT + o)) * HW + (size_t)gy * WW + gx;
            *(float2*)(out + base0) =
                make_float2((float)acc[i][j][0], (float)acc[i][j][1]);
            *(float2*)(out + base0 + (size_t)8 * HW) =
                make_float2((float)acc[i][j][2], (float)acc[i][j][3]);
        }
    }
}

// ---------------------------------------------------------------------------
// Launch
// ---------------------------------------------------------------------------
extern "C" void kernel_launch(void* const* d_in, const int* in_sizes, int n_in,
                              void* d_out, int out_size) {
    const float* x  = (const float*)d_in[0];
    const float* pf = (const float*)d_in[2];
    const float* of = (const float*)d_in[3];
    float* out = (float*)d_out;

    cudaFuncSetAttribute(stage2_kernel,
                         cudaFuncAttributeMaxDynamicSharedMemorySize, SMEM_TOTAL);

    const int nquads = BB * HW / 4;
    pack_x_kernel<<<(nquads + 255) / 256, 256>>>(x);

    pack_pf_kernel<<<(NP * 9 + 255) / 256, 256>>>(pf);
    pack_wA_kernel<<<(COUT * WA_STRIDE + 255) / 256, 256>>>(of);

    stage1_kernel<<<dim3(GG, GG, BB), dim3(PTCH, PTCH)>>>();

    stage2_kernel<<<dim3(WW / 16, HH / 16, BB), 256, SMEM_TOTAL>>>(out);
}

// round 6
// speedup vs baseline: 1.1306x; 1.1306x over previous
#include <cuda_runtime.h>
#include <cstdint>

// Problem constants
#define BB   8
#define CIN  64
#define COUT 128
#define HH   224
#define WW   224
#define HW   (HH * WW)
#define PTCH 16
#define GG   14     // 14x14 patch grid
#define NP   196

typedef unsigned long long u64;
typedef unsigned int u32;

// ---------------------------------------------------------------------------
// Scratch (device globals — no allocations allowed)
// ---------------------------------------------------------------------------
__device__ u64 g_sx[BB * HW];                          // packed sign(x)
__device__ u64 g_pw[NP * 9];                           // packed sign(patch_filters)
__device__ __align__(16) int8_t g_bsa[(size_t)BB * HW * CIN];  // ternary bsa, channels-last

#define WA_STRIDE 592                                  // 576 + pad; 20 quad-banks mod 32 -> conflict-free
__device__ __align__(16) int8_t g_wA[COUT * WA_STRIDE];  // int8 weights, row o, k = t*64+h*32+kl

// ---------------------------------------------------------------------------
// Kernel 0: pack sign bits of x (4 pixels/thread, float4 loads)
// ---------------------------------------------------------------------------
__global__ void __launch_bounds__(256) pack_x_kernel(const float* __restrict__ x) {
    int q = blockIdx.x * blockDim.x + threadIdx.x;
    const int NQ = BB * HW / 4;
    if (q >= NQ) return;
    int pix = q * 4;
    int b   = pix / HW;
    int rem = pix - b * HW;
    const float4* xp = (const float4*)(x + (size_t)b * CIN * HW + rem);
    u64 w0 = 0, w1 = 0, w2 = 0, w3 = 0;
#pragma unroll
    for (int c = 0; c < CIN; c++) {
        float4 v = xp[(size_t)c * (HW / 4)];
        w0 |= (u64)(__float_as_uint(v.x) >> 31) << c;
        w1 |= (u64)(__float_as_uint(v.y) >> 31) << c;
        w2 |= (u64)(__float_as_uint(v.z) >> 31) << c;
        w3 |= (u64)(__float_as_uint(v.w) >> 31) << c;
    }
    g_sx[pix + 0] = w0;
    g_sx[pix + 1] = w1;
    g_sx[pix + 2] = w2;
    g_sx[pix + 3] = w3;
}

// ---------------------------------------------------------------------------
// Kernel 0b: pack patch-filter sign bits (for stage1)
// ---------------------------------------------------------------------------
__global__ void pack_pf_kernel(const float* __restrict__ pf) {
    int i = blockIdx.x * blockDim.x + threadIdx.x;
    if (i >= NP * 9) return;
    int p = i / 9, t = i - p * 9;
    u64 w = 0;
#pragma unroll
    for (int c = 0; c < CIN; c++) {
        unsigned sb = __float_as_uint(pf[((size_t)c * NP + p) * 9 + t]) >> 31;
        w |= (u64)sb << c;
    }
    g_pw[i] = w;
}

// ---------------------------------------------------------------------------
// Kernel 0c: pack output-conv weights as int8 rows wA[o][kg], kg = t*64 + c.
// ---------------------------------------------------------------------------
__global__ void pack_wA_kernel(const float* __restrict__ of) {
    int idx = blockIdx.x * blockDim.x + threadIdx.x;
    if (idx >= COUT * WA_STRIDE) return;
    int o = idx / WA_STRIDE, kg = idx - o * WA_STRIDE;
    int8_t v = 0;
    if (kg < 576) {
        int t = kg >> 6, c = kg & 63;
        unsigned sb = __float_as_uint(of[((size_t)o * CIN + c) * 9 + t]) >> 31;
        v = sb ? (int8_t)-1 : (int8_t)1;
    }
    g_wA[idx] = v;
}

// ---------------------------------------------------------------------------
// Kernel 1: per-patch depthwise binary 3x3 conv -> ternary bsa as int8.
// ---------------------------------------------------------------------------
__global__ void __launch_bounds__(256) stage1_kernel() {
    __shared__ u64 tile[PTCH][PTCH];
    __shared__ u64 pw9[9];

    const int gx = blockIdx.x, gy = blockIdx.y, b = blockIdx.z;
    const int j = threadIdx.x, i = threadIdx.y;
    const int tid = i * PTCH + j;
    const int patch = gy * GG + gx;

    const int y = gy * PTCH + i;
    const int x = gx * PTCH + j;
    const int pixbase = b * HW;

    tile[i][j] = g_sx[pixbase + y * WW + x];
    if (tid < 9) pw9[tid] = g_pw[patch * 9 + tid];
    __syncthreads();

    u64 c0 = 0, c1 = 0, c2 = 0, c3 = 0;
#pragma unroll
    for (int di = 0; di < 3; di++) {
#pragma unroll
        for (int dj = 0; dj < 3; dj++) {
            int li = i + di - 1, lj = j + dj - 1;
            if (li >= 0 && li < PTCH && lj >= 0 && lj < PTCH) {
                u64 d = tile[li][lj] ^ pw9[di * 3 + dj];
                u64 carry = d, u;
                u = c0 & carry; c0 ^= carry; carry = u;
                u = c1 & carry; c1 ^= carry; carry = u;
                u = c2 & carry; c2 ^= carry; carry = u;
                c3 ^= carry;
            }
        }
    }

    const int ni = (i == 0 || i == PTCH - 1) ? 2 : 3;
    const int nj = (j == 0 || j == PTCH - 1) ? 2 : 3;
    const int n  = ni * nj;

    u64 m, s;
    if (n == 9) {
        m = ~0ULL;
        s = c3 | (c2 & (c1 | c0));
    } else if (n == 6) {
        m = ~(c0 & c1 & ~c2);
        s = c2;
    } else { // n == 4
        m = ~(c1 & ~c0 & ~c2);
        s = (c0 & c1) | c2;
    }

    // Emit ternary int8: m ? (s ? -1 : +1) : 0, channels-last.
    u32 w32[16];
#pragma unroll
    for (int wi = 0; wi < 16; wi++) {
        u32 v = 0;
#pragma unroll
        for (int bi = 0; bi < 4; bi++) {
            int c = wi * 4 + bi;
            u32 mb = (u32)((m >> c) & 1ULL);
            u32 sb = (u32)((s >> c) & 1ULL);
            u32 byte = mb ? (sb ? 0xFFu : 0x01u) : 0u;
            v |= byte << (bi * 8);
        }
        w32[wi] = v;
    }
    uint4* dst = (uint4*)(g_bsa + ((size_t)(pixbase + y * WW + x)) * CIN);
    dst[0] = make_uint4(w32[0],  w32[1],  w32[2],  w32[3]);
    dst[1] = make_uint4(w32[4],  w32[5],  w32[6],  w32[7]);
    dst[2] = make_uint4(w32[8],  w32[9],  w32[10], w32[11]);
    dst[3] = make_uint4(w32[12], w32[13], w32[14], w32[15]);
}

// ---------------------------------------------------------------------------
// Kernel 2: final conv as int8 implicit GEMM via mma.sync + ldmatrix.
//   M = COUT (128 = 8 m16), N = 256 pixels (16x16 tile = 32 n8), K = 576.
//   Block: 512 threads = 2 M-warps x 8 N-warps; warp tile 4 m16 x 4 n8
//   (each N-warp owns 2 pixel rows x 16 x). All fragment loads via LDSM.x4:
//   6 load instrs / warp / K-step (4 A + 2 B).
// ---------------------------------------------------------------------------
#define HALO_STRIDE 80
#define SMEM_A_BYTES (COUT * WA_STRIDE)          // 75776
#define SMEM_HALO_BYTES (18 * 18 * HALO_STRIDE)  // 25920
#define SMEM_TOTAL (SMEM_A_BYTES + SMEM_HALO_BYTES)

__device__ __forceinline__ void mma_s8(int* d, const u32* a, const u32* b) {
    asm volatile(
        "mma.sync.aligned.m16n8k32.row.col.s32.s8.s8.s32 "
        "{%0,%1,%2,%3}, {%4,%5,%6,%7}, {%8,%9}, {%0,%1,%2,%3};\n"
        : "+r"(d[0]), "+r"(d[1]), "+r"(d[2]), "+r"(d[3])
        : "r"(a[0]), "r"(a[1]), "r"(a[2]), "r"(a[3]),
          "r"(b[0]), "r"(b[1]));
}

__device__ __forceinline__ void ldsm_x4(u32 addr, u32& r0, u32& r1, u32& r2, u32& r3) {
    asm volatile(
        "ldmatrix.sync.aligned.m8n8.x4.shared.b16 {%0,%1,%2,%3}, [%4];"
        : "=r"(r0), "=r"(r1), "=r"(r2), "=r"(r3) : "r"(addr));
}

__global__ void __launch_bounds__(512, 1) stage2_kernel(float* __restrict__ out) {
    extern __shared__ char sm[];
    const u32 smb = (u32)__cvta_generic_to_shared(sm);

    const int tid = threadIdx.x;
    const int b  = blockIdx.z;
    const int x0 = blockIdx.x * 16, y0 = blockIdx.y * 16;

    // Load weights into smem
    {
        const uint4* src = (const uint4*)g_wA;
        uint4* dst = (uint4*)sm;
        for (int i = tid; i < SMEM_A_BYTES / 16; i += 512) dst[i] = src[i];
    }
    // Load 18x18 pixel halo of bsa (64 B each), zero-padded at image edges
    if (tid < 324) {
        int hy = tid / 18, hx = tid - hy * 18;
        int gy = y0 - 1 + hy, gx = x0 - 1 + hx;
        uint4 v0 = make_uint4(0, 0, 0, 0), v1 = v0, v2 = v0, v3 = v0;
        if (gy >= 0 && gy < HH && gx >= 0 && gx < WW) {
            const uint4* s = (const uint4*)(g_bsa + ((size_t)((b * HH + gy) * WW + gx)) * CIN);
            v0 = s[0]; v1 = s[1]; v2 = s[2]; v3 = s[3];
        }
        uint4* d = (uint4*)(sm + SMEM_A_BYTES + (hy * 18 + hx) * HALO_STRIDE);
        d[0] = v0; d[1] = v1; d[2] = v2; d[3] = v3;
    }
    __syncthreads();

    const int warp = tid >> 5, lane = tid & 31;
    const int wm = warp & 1, wn = warp >> 1;       // 2 M-warps x 8 N-warps
    const int gid = lane >> 2, tig = lane & 3;
    const int o_base = wm * 64;

    // A mtile i (16 o-rows x 32B k-chunk as 4 8x16B mats):
    //   lanes 0-15 -> rows (lane&15), k-seg 0; lanes 16-31 -> same rows, seg 16.
    u32 aaddr[4];
#pragma unroll
    for (int i = 0; i < 4; i++)
        aaddr[i] = smb + (u32)((o_base + i * 16 + (lane & 15)) * WA_STRIDE
                               + ((lane >> 4) << 4));

    // B: N-warp wn owns pixel rows {2wn, 2wn+1}. One LDSM.x4 per row covers
    // 16 pixels x 32 k-bytes = 2 n8 tiles:
    //   lanes 0-7: x 0-7 seg0; 8-15: seg16; 16-23: x 8-15 seg0; 24-31: seg16.
    u32 baddr[2];
    int pty[2];
#pragma unroll
    for (int jr = 0; jr < 2; jr++) {
        int ty = wn * 2 + jr;
        pty[jr] = ty;
        baddr[jr] = smb + SMEM_A_BYTES
                  + (u32)((ty * 18 + ((lane >> 4) << 3) + (lane & 7)) * HALO_STRIDE
                          + ((lane >> 3) & 1) * 16);
    }

    int acc[4][4][4];
#pragma unroll
    for (int i = 0; i < 4; i++)
#pragma unroll
        for (int j = 0; j < 4; j++)
#pragma unroll
            for (int k = 0; k < 4; k++) acc[i][j][k] = 0;

    // K loop: ks -> (tap t = ks>>1, half h = ks&1). All offsets constant-folded.
#pragma unroll
    for (int ks = 0; ks < 18; ks++) {
        const int t = ks >> 1, h = ks & 1;
        const int dy = t / 3, dx = t - dy * 3;
        const u32 bofs = (u32)((dy * 18 + dx) * HALO_STRIDE + h * 32);
        const u32 aofs = (u32)(ks * 32);

        u32 a[4][4];
#pragma unroll
        for (int i = 0; i < 4; i++)
            ldsm_x4(aaddr[i] + aofs, a[i][0], a[i][1], a[i][2], a[i][3]);

        u32 bb[2][4];   // bb[jr][0..1] = ntile x0-7; [2..3] = ntile x8-15
#pragma unroll
        for (int jr = 0; jr < 2; jr++)
            ldsm_x4(baddr[jr] + bofs, bb[jr][0], bb[jr][1], bb[jr][2], bb[jr][3]);

#pragma unroll
        for (int i = 0; i < 4; i++)
#pragma unroll
            for (int j = 0; j < 4; j++)
                mma_s8(acc[i][j], a[i], &bb[j >> 1][(j & 1) * 2]);
    }

    // Epilogue: C frag row = o, col = pixel x -> coalesced float2 stores.
#pragma unroll
    for (int i = 0; i < 4; i++) {
        int o = o_base + i * 16 + gid;
#pragma unroll
        for (int j = 0; j < 4; j++) {
            int gy = y0 + pty[j >> 1];
            int gx = x0 + (j & 1) * 8 + tig * 2;
            size_t base0 = ((size_t)(b * COUT + o)) * HW + (size_t)gy * WW + gx;
            *(float2*)(out + base0) =
                make_float2((float)acc[i][j][0], (float)acc[i][j][1]);
            *(float2*)(out + base0 + (size_t)8 * HW) =
                make_float2((float)acc[i][j][2], (float)acc[i][j][3]);
        }
    }
}

// ---------------------------------------------------------------------------
// Launch
// ---------------------------------------------------------------------------
extern "C" void kernel_launch(void* const* d_in, const int* in_sizes, int n_in,
                              void* d_out, int out_size) {
    const float* x  = (const float*)d_in[0];
    const float* pf = (const float*)d_in[2];
    const float* of = (const float*)d_in[3];
    float* out = (float*)d_out;

    cudaFuncSetAttribute(stage2_kernel,
                         cudaFuncAttributeMaxDynamicSharedMemorySize, SMEM_TOTAL);

    const int nquads = BB * HW / 4;
    pack_x_kernel<<<(nquads + 255) / 256, 256>>>(x);

    pack_pf_kernel<<<(NP * 9 + 255) / 256, 256>>>(pf);
    pack_wA_kernel<<<(COUT * WA_STRIDE + 255) / 256, 256>>>(of);

    stage1_kernel<<<dim3(GG, GG, BB), dim3(PTCH, PTCH)>>>();

    stage2_kernel<<<dim3(WW / 16, HH / 16, BB), 512, SMEM_TOTAL>>>(out);
}

// round 8
// speedup vs baseline: 1.4462x; 1.2791x over previous
#include <cuda_runtime.h>
#include <cstdint>

// Problem constants
#define BB   8
#define CIN  64
#define COUT 128
#define HH   224
#define WW   224
#define HW   (HH * WW)
#define PTCH 16
#define GG   14     // 14x14 patch grid
#define NP   196
#define NTILES (BB * GG * GG)   // 1568
#define NBLK 148                // persistent blocks (one per SM)

typedef unsigned long long u64;
typedef unsigned int u32;

// ---------------------------------------------------------------------------
// Scratch (device globals — no allocations allowed)
// ---------------------------------------------------------------------------
__device__ u64 g_pw[NP * 9];                           // packed sign(patch_filters)
__device__ __align__(16) int8_t g_bsa[(size_t)BB * HW * CIN];  // ternary bsa, channels-last

#define WA_STRIDE 592                                  // 576 + pad; 20 quad-banks mod 32 -> conflict-free
__device__ __align__(16) int8_t g_wA[COUT * WA_STRIDE];  // int8 weights, row o, k = t*64+h*32+kl

// ---------------------------------------------------------------------------
// cp.async helpers
// ---------------------------------------------------------------------------
__device__ __forceinline__ void cp16(u32 dst, const void* src, int srcsize) {
    asm volatile("cp.async.cg.shared.global [%0], [%1], 16, %2;\n"
                 :: "r"(dst), "l"(src), "r"(srcsize));
}
__device__ __forceinline__ void cp_commit() { asm volatile("cp.async.commit_group;\n"); }
__device__ __forceinline__ void cp_wait0()  { asm volatile("cp.async.wait_group 0;\n"); }

// ---------------------------------------------------------------------------
// Kernel 0b: pack patch-filter sign bits (for stage1)
// ---------------------------------------------------------------------------
__global__ void pack_pf_kernel(const float* __restrict__ pf) {
    int i = blockIdx.x * blockDim.x + threadIdx.x;
    if (i >= NP * 9) return;
    int p = i / 9, t = i - p * 9;
    u64 w = 0;
#pragma unroll
    for (int c = 0; c < CIN; c++) {
        unsigned sb = __float_as_uint(pf[((size_t)c * NP + p) * 9 + t]) >> 31;
        w |= (u64)sb << c;
    }
    g_pw[i] = w;
}

// ---------------------------------------------------------------------------
// Kernel 0c: pack output-conv weights as int8 rows wA[o][kg], kg = t*64 + c.
// ---------------------------------------------------------------------------
__global__ void pack_wA_kernel(const float* __restrict__ of) {
    int idx = blockIdx.x * blockDim.x + threadIdx.x;
    if (idx >= COUT * WA_STRIDE) return;
    int o = idx / WA_STRIDE, kg = idx - o * WA_STRIDE;
    int8_t v = 0;
    if (kg < 576) {
        int t = kg >> 6, c = kg & 63;
        unsigned sb = __float_as_uint(of[((size_t)o * CIN + c) * 9 + t]) >> 31;
        v = sb ? (int8_t)-1 : (int8_t)1;
    }
    g_wA[idx] = v;
}

// ---------------------------------------------------------------------------
// Kernel 1 (fused sign-pack): read x directly, pack 64-channel signs per
// pixel in-register, depthwise binary 3x3 per patch, emit ternary int8 bsa.
// ---------------------------------------------------------------------------
__global__ void __launch_bounds__(256) stage1_kernel(const float* __restrict__ x) {
    __shared__ u64 tile[PTCH][PTCH];
    __shared__ u64 pw9[9];

    const int gx = blockIdx.x, gy = blockIdx.y, b = blockIdx.z;
    const int j = threadIdx.x, i = threadIdx.y;
    const int tid = i * PTCH + j;
    const int patch = gy * GG + gx;

    const int y = gy * PTCH + i;
    const int px = gx * PTCH + j;
    const int pixbase = b * HW;

    // Pack sign bits of this pixel across 64 channels.
    {
        const float* xp = x + (size_t)b * CIN * HW + y * WW + px;
        u64 w = 0;
#pragma unroll
        for (int c = 0; c < CIN; c++)
            w |= (u64)(__float_as_uint(xp[(size_t)c * HW]) >> 31) << c;
        tile[i][j] = w;
    }
    if (tid < 9) pw9[tid] = g_pw[patch * 9 + tid];
    __syncthreads();

    u64 c0 = 0, c1 = 0, c2 = 0, c3 = 0;
#pragma unroll
    for (int di = 0; di < 3; di++) {
#pragma unroll
        for (int dj = 0; dj < 3; dj++) {
            int li = i + di - 1, lj = j + dj - 1;
            if (li >= 0 && li < PTCH && lj >= 0 && lj < PTCH) {
                u64 d = tile[li][lj] ^ pw9[di * 3 + dj];
                u64 carry = d, u;
                u = c0 & carry; c0 ^= carry; carry = u;
                u = c1 & carry; c1 ^= carry; carry = u;
                u = c2 & carry; c2 ^= carry; carry = u;
                c3 ^= carry;
            }
        }
    }

    const int ni = (i == 0 || i == PTCH - 1) ? 2 : 3;
    const int nj = (j == 0 || j == PTCH - 1) ? 2 : 3;
    const int n  = ni * nj;

    u64 m, s;
    if (n == 9) {
        m = ~0ULL;
        s = c3 | (c2 & (c1 | c0));
    } else if (n == 6) {
        m = ~(c0 & c1 & ~c2);
        s = c2;
    } else { // n == 4
        m = ~(c1 & ~c0 & ~c2);
        s = (c0 & c1) | c2;
    }

    // Emit ternary int8: m ? (s ? -1 : +1) : 0, channels-last.
    u32 w32[16];
#pragma unroll
    for (int wi = 0; wi < 16; wi++) {
        u32 v = 0;
#pragma unroll
        for (int bi = 0; bi < 4; bi++) {
            int c = wi * 4 + bi;
            u32 mb = (u32)((m >> c) & 1ULL);
            u32 sb = (u32)((s >> c) & 1ULL);
            u32 byte = mb ? (sb ? 0xFFu : 0x01u) : 0u;
            v |= byte << (bi * 8);
        }
        w32[wi] = v;
    }
    uint4* dst = (uint4*)(g_bsa + ((size_t)(pixbase + y * WW + px)) * CIN);
    dst[0] = make_uint4(w32[0],  w32[1],  w32[2],  w32[3]);
    dst[1] = make_uint4(w32[4],  w32[5],  w32[6],  w32[7]);
    dst[2] = make_uint4(w32[8],  w32[9],  w32[10], w32[11]);
    dst[3] = make_uint4(w32[12], w32[13], w32[14], w32[15]);
}

// ---------------------------------------------------------------------------
// Kernel 2: PERSISTENT int8 implicit GEMM via mma.sync + ldmatrix.
//   Grid = 148 blocks x 512 threads. Weights loaded to smem ONCE per block;
//   loop over tiles with double-buffered cp.async halo prefetch.
//   Per tile: M = 128 (8 m16), N = 256 pixels (16x16 -> 32 n8), K = 576.
//   Warps: 2 M x 8 N; warp tile 4 m16 x 4 n8; LDSM.x4 fragment loads.
// ---------------------------------------------------------------------------
#define HALO_STRIDE 80
#define SMEM_A_BYTES (COUT * WA_STRIDE)          // 75776
#define SMEM_HALO_BYTES (18 * 18 * HALO_STRIDE)  // 25920
#define SMEM_TOTAL (SMEM_A_BYTES + 2 * SMEM_HALO_BYTES)   // 127616

__device__ __forceinline__ void mma_s8(int* d, const u32* a, const u32* b) {
    asm volatile(
        "mma.sync.aligned.m16n8k32.row.col.s32.s8.s8.s32 "
        "{%0,%1,%2,%3}, {%4,%5,%6,%7}, {%8,%9}, {%0,%1,%2,%3};\n"
        : "+r"(d[0]), "+r"(d[1]), "+r"(d[2]), "+r"(d[3])
        : "r"(a[0]), "r"(a[1]), "r"(a[2]), "r"(a[3]),
          "r"(b[0]), "r"(b[1]));
}

__device__ __forceinline__ void ldsm_x4(u32 addr, u32& r0, u32& r1, u32& r2, u32& r3) {
    asm volatile(
        "ldmatrix.sync.aligned.m8n8.x4.shared.b16 {%0,%1,%2,%3}, [%4];"
        : "=r"(r0), "=r"(r1), "=r"(r2), "=r"(r3) : "r"(addr));
}

// Prefetch one tile's 18x18 bsa halo into smem buffer (cp.async, zfill OOB).
__device__ __forceinline__ void halo_load(int t, u32 dstbase, int tid) {
    int b = t / NP, r = t - b * NP;
    int ty0 = (r / GG) * 16 - 1, tx0 = (r - (r / GG) * GG) * 16 - 1;
    for (int idx = tid; idx < 324 * 4; idx += 512) {
        int pixel = idx >> 2, c = idx & 3;
        int hy = pixel / 18, hx = pixel - hy * 18;
        int gy = ty0 + hy, gx = tx0 + hx;
        bool ok = (gy >= 0) & (gy < HH) & (gx >= 0) & (gx < WW);
        const int8_t* src = ok
            ? g_bsa + ((size_t)((b * HH + gy) * WW + gx)) * CIN + c * 16
            : g_bsa;
        cp16(dstbase + pixel * HALO_STRIDE + c * 16, src, ok ? 16 : 0);
    }
}

__global__ void __launch_bounds__(512, 1) stage2_kernel(float* __restrict__ out) {
    extern __shared__ char sm[];
    const u32 smb = (u32)__cvta_generic_to_shared(sm);
    const int tid = threadIdx.x;

    // Load weights once (cp.async) + first halo.
    for (int i = tid; i < SMEM_A_BYTES / 16; i += 512)
        cp16(smb + i * 16, g_wA + i * 16, 16);
    halo_load(blockIdx.x, smb + SMEM_A_BYTES, tid);
    cp_commit();
    cp_wait0();
    __syncthreads();

    const int warp = tid >> 5, lane = tid & 31;
    const int wm = warp & 1, wn = warp >> 1;       // 2 M-warps x 8 N-warps
    const int gid = lane >> 2, tig = lane & 3;
    const int o_base = wm * 64;

    // A LDSM addresses (fixed for the whole kernel).
    u32 aaddr[4];
#pragma unroll
    for (int i = 0; i < 4; i++)
        aaddr[i] = smb + (u32)((o_base + i * 16 + (lane & 15)) * WA_STRIDE
                               + ((lane >> 4) << 4));

    // B LDSM lane offsets relative to halo-buffer base.
    u32 brel[2];
    int pty[2];
#pragma unroll
    for (int jr = 0; jr < 2; jr++) {
        int ty = wn * 2 + jr;
        pty[jr] = ty;
        brel[jr] = (u32)((ty * 18 + ((lane >> 4) << 3) + (lane & 7)) * HALO_STRIDE
                         + ((lane >> 3) & 1) * 16);
    }

    int w = 0;
    for (int t = blockIdx.x; t < NTILES; t += NBLK, w++) {
        const u32 curbase = smb + SMEM_A_BYTES + (u32)((w & 1) * SMEM_HALO_BYTES);

        // Prefetch next tile's halo into the other buffer.
        if (t + NBLK < NTILES)
            halo_load(t + NBLK, smb + SMEM_A_BYTES + (u32)(((w + 1) & 1) * SMEM_HALO_BYTES), tid);
        cp_commit();

        int acc[4][4][4];
#pragma unroll
        for (int i = 0; i < 4; i++)
#pragma unroll
            for (int j = 0; j < 4; j++)
#pragma unroll
                for (int k = 0; k < 4; k++) acc[i][j][k] = 0;

#pragma unroll
        for (int ks = 0; ks < 18; ks++) {
            const int tp = ks >> 1, h = ks & 1;
            const int dy = tp / 3, dx = tp - dy * 3;
            const u32 bofs = (u32)((dy * 18 + dx) * HALO_STRIDE + h * 32);
            const u32 aofs = (u32)(ks * 32);

            u32 a[4][4];
#pragma unroll
            for (int i = 0; i < 4; i++)
                ldsm_x4(aaddr[i] + aofs, a[i][0], a[i][1], a[i][2], a[i][3]);

            u32 bb[2][4];
#pragma unroll
            for (int jr = 0; jr < 2; jr++)
                ldsm_x4(curbase + brel[jr] + bofs, bb[jr][0], bb[jr][1], bb[jr][2], bb[jr][3]);

#pragma unroll
            for (int i = 0; i < 4; i++)
#pragma unroll
                for (int j = 0; j < 4; j++)
                    mma_s8(acc[i][j], a[i], &bb[j >> 1][(j & 1) * 2]);
        }

        // Epilogue
        {
            int b = t / NP, r = t - b * NP;
            int y0 = (r / GG) * 16, x0 = (r - (r / GG) * GG) * 16;
#pragma unroll
            for (int i = 0; i < 4; i++) {
                int o = o_base + i * 16 + gid;
#pragma unroll
                for (int j = 0; j < 4; j++) {
                    int gy = y0 + pty[j >> 1];
                    int gx = x0 + (j & 1) * 8 + tig * 2;
                    size_t base0 = ((size_t)(b * COUT + o)) * HW + (size_t)gy * WW + gx;
                    *(float2*)(out + base0) =
                        make_float2((float)acc[i][j][0], (float)acc[i][j][1]);
                    *(float2*)(out + base0 + (size_t)8 * HW) =
                        make_float2((float)acc[i][j][2], (float)acc[i][j][3]);
                }
            }
        }

        // Single barrier suffices: cp_wait0 (this thread's prefetch landed) +
        // barrier (everyone done reading curbase, prefetched data visible).
        cp_wait0();
        __syncthreads();
    }
}

// ---------------------------------------------------------------------------
// Launch
// ---------------------------------------------------------------------------
extern "C" void kernel_launch(void* const* d_in, const int* in_sizes, int n_in,
                              void* d_out, int out_size) {
    const float* x  = (const float*)d_in[0];
    const float* pf = (const float*)d_in[2];
    const float* of = (const float*)d_in[3];
    float* out = (float*)d_out;

    cudaFuncSetAttribute(stage2_kernel,
                         cudaFuncAttributeMaxDynamicSharedMemorySize, SMEM_TOTAL);

    pack_pf_kernel<<<(NP * 9 + 255) / 256, 256>>>(pf);
    pack_wA_kernel<<<(COUT * WA_STRIDE + 255) / 256, 256>>>(of);

    stage1_kernel<<<dim3(GG, GG, BB), dim3(PTCH, PTCH)>>>(x);

    stage2_kernel<<<NBLK, 512, SMEM_TOTAL>>>(out);
}

// round 10
// speedup vs baseline: 1.4465x; 1.0002x over previous
#include <cuda_runtime.h>
#include <cstdint>

// Problem constants
#define BB   8
#define CIN  64
#define COUT 128
#define HH   224
#define WW   224
#define HW   (HH * WW)
#define PTCH 16
#define GG   14     // 14x14 patch grid
#define NP   196
#define NTILES (BB * GG * GG)   // 1568
#define NBLK2 296               // persistent stage2 blocks (2 per SM)

typedef unsigned long long u64;
typedef unsigned int u32;

// ---------------------------------------------------------------------------
// Scratch (device globals — no allocations allowed)
// ---------------------------------------------------------------------------
__device__ u64 g_pw[NP * 9];                           // packed sign(patch_filters)
__device__ __align__(16) int8_t g_bsa[(size_t)BB * HW * CIN];  // ternary bsa, channels-last

#define WA_STRIDE 592                                  // 576 + pad; 20 quad-banks mod 32 -> conflict-free
__device__ __align__(16) int8_t g_wA[COUT * WA_STRIDE];  // int8 weights, row o, k = t*64+h*32+kl

// ---------------------------------------------------------------------------
// cp.async helpers
// ---------------------------------------------------------------------------
__device__ __forceinline__ void cp16(u32 dst, const void* src, int srcsize) {
    asm volatile("cp.async.cg.shared.global [%0], [%1], 16, %2;\n"
                 :: "r"(dst), "l"(src), "r"(srcsize));
}
__device__ __forceinline__ void cp_commit() { asm volatile("cp.async.commit_group;\n"); }
__device__ __forceinline__ void cp_wait0()  { asm volatile("cp.async.wait_group 0;\n"); }

// ---------------------------------------------------------------------------
// Kernel 0b: pack patch-filter sign bits (for stage1)
// ---------------------------------------------------------------------------
__global__ void pack_pf_kernel(const float* __restrict__ pf) {
    int i = blockIdx.x * blockDim.x + threadIdx.x;
    if (i >= NP * 9) return;
    int p = i / 9, t = i - p * 9;
    u64 w = 0;
#pragma unroll
    for (int c = 0; c < CIN; c++) {
        unsigned sb = __float_as_uint(pf[((size_t)c * NP + p) * 9 + t]) >> 31;
        w |= (u64)sb << c;
    }
    g_pw[i] = w;
}

// ---------------------------------------------------------------------------
// Kernel 0c: pack output-conv weights as int8 rows wA[o][kg], kg = t*64 + c.
// ---------------------------------------------------------------------------
__global__ void pack_wA_kernel(const float* __restrict__ of) {
    int idx = blockIdx.x * blockDim.x + threadIdx.x;
    if (idx >= COUT * WA_STRIDE) return;
    int o = idx / WA_STRIDE, kg = idx - o * WA_STRIDE;
    int8_t v = 0;
    if (kg < 576) {
        int t = kg >> 6, c = kg & 63;
        unsigned sb = __float_as_uint(of[((size_t)o * CIN + c) * 9 + t]) >> 31;
        v = sb ? (int8_t)-1 : (int8_t)1;
    }
    g_wA[idx] = v;
}

// ---------------------------------------------------------------------------
// Kernel 1 (fused sign-pack, float4): block = 128 threads covers a 16x32
// pixel region (2 adjacent patches). Each thread: 4 consecutive x pixels.
// ---------------------------------------------------------------------------
__global__ void __launch_bounds__(128) stage1_kernel(const float* __restrict__ x) {
    __shared__ u64 tile[PTCH][32];
    __shared__ u64 pws[2][9];

    const int tid = threadIdx.x;
    const int ty  = tid >> 3;          // 0..15  (pixel row in region)
    const int txg = tid & 7;           // 0..7   (4-pixel group)
    const int b   = blockIdx.z;
    const int y   = blockIdx.y * PTCH + ty;
    const int gx0 = blockIdx.x * 32 + txg * 4;

    // Pack sign bits for 4 consecutive pixels across 64 channels.
    {
        const float* xp = x + (size_t)b * CIN * HW + (size_t)y * WW + gx0;
        u64 w0 = 0, w1 = 0, w2 = 0, w3 = 0;
#pragma unroll
        for (int c = 0; c < CIN; c++) {
            float4 v = *(const float4*)(xp + (size_t)c * HW);
            w0 |= (u64)(__float_as_uint(v.x) >> 31) << c;
            w1 |= (u64)(__float_as_uint(v.y) >> 31) << c;
            w2 |= (u64)(__float_as_uint(v.z) >> 31) << c;
            w3 |= (u64)(__float_as_uint(v.w) >> 31) << c;
        }
        int jb = txg * 4;
        tile[ty][jb + 0] = w0;
        tile[ty][jb + 1] = w1;
        tile[ty][jb + 2] = w2;
        tile[ty][jb + 3] = w3;
    }
    if (tid < 18) {
        int ph = tid / 9, t = tid - ph * 9;
        pws[ph][t] = g_pw[((blockIdx.y) * GG + blockIdx.x * 2 + ph) * 9 + t];
    }
    __syncthreads();

    const int ni = (ty == 0 || ty == PTCH - 1) ? 2 : 3;

#pragma unroll
    for (int e = 0; e < 4; e++) {
        const int j  = txg * 4 + e;    // 0..31 local x
        const int jj = j & 15;         // patch-local x
        const int ph = j >> 4;         // which patch (0/1)

        u64 c0 = 0, c1 = 0, c2 = 0, c3 = 0;
#pragma unroll
        for (int di = 0; di < 3; di++) {
#pragma unroll
            for (int dj = 0; dj < 3; dj++) {
                int li = ty + di - 1, ljj = jj + dj - 1;
                if (li >= 0 && li < PTCH && ljj >= 0 && ljj < PTCH) {
                    u64 d = tile[li][j + dj - 1] ^ pws[ph][di * 3 + dj];
                    u64 carry = d, u;
                    u = c0 & carry; c0 ^= carry; carry = u;
                    u = c1 & carry; c1 ^= carry; carry = u;
                    u = c2 & carry; c2 ^= carry; carry = u;
                    c3 ^= carry;
                }
            }
        }

        const int nj = (jj == 0 || jj == PTCH - 1) ? 2 : 3;
        const int n  = ni * nj;

        u64 m, s;
        if (n == 9) {
            m = ~0ULL;
            s = c3 | (c2 & (c1 | c0));
        } else if (n == 6) {
            m = ~(c0 & c1 & ~c2);
            s = c2;
        } else { // n == 4
            m = ~(c1 & ~c0 & ~c2);
            s = (c0 & c1) | c2;
        }

        u32 w32[16];
#pragma unroll
        for (int wi = 0; wi < 16; wi++) {
            u32 v = 0;
#pragma unroll
            for (int bi = 0; bi < 4; bi++) {
                int c = wi * 4 + bi;
                u32 mb = (u32)((m >> c) & 1ULL);
                u32 sb = (u32)((s >> c) & 1ULL);
                u32 byte = mb ? (sb ? 0xFFu : 0x01u) : 0u;
                v |= byte << (bi * 8);
            }
            w32[wi] = v;
        }
        uint4* dst = (uint4*)(g_bsa + ((size_t)((b * HH + y) * WW + gx0 + e)) * CIN);
        dst[0] = make_uint4(w32[0],  w32[1],  w32[2],  w32[3]);
        dst[1] = make_uint4(w32[4],  w32[5],  w32[6],  w32[7]);
        dst[2] = make_uint4(w32[8],  w32[9],  w32[10], w32[11]);
        dst[3] = make_uint4(w32[12], w32[13], w32[14], w32[15]);
    }
}

// ---------------------------------------------------------------------------
// Kernel 2: PERSISTENT split-M int8 implicit GEMM (mma.sync + ldmatrix).
//   Grid = 296 blocks (2/SM) x 256 threads. Each block owns a FIXED 64-channel
//   half (mh = blockIdx.x & 1) -> half weights in smem (37.9 KB), and iterates
//   tiles q, q+148, ... with double-buffered cp.async halo prefetch.
//   Per unit: M = 64 (4 m16), N = 256 pixels (32 n8), K = 576.
//   Two independent blocks per SM overlap each other's barriers/epilogues.
// ---------------------------------------------------------------------------
#define HALO_STRIDE 80
#define SMEM_A_BYTES (64 * WA_STRIDE)            // 37888 (half the channels)
#define SMEM_HALO_BYTES (18 * 18 * HALO_STRIDE)  // 25920
#define SMEM_TOTAL (SMEM_A_BYTES + 2 * SMEM_HALO_BYTES)   // 89728

__device__ __forceinline__ void mma_s8(int* d, const u32* a, const u32* b) {
    asm volatile(
        "mma.sync.aligned.m16n8k32.row.col.s32.s8.s8.s32 "
        "{%0,%1,%2,%3}, {%4,%5,%6,%7}, {%8,%9}, {%0,%1,%2,%3};\n"
        : "+r"(d[0]), "+r"(d[1]), "+r"(d[2]), "+r"(d[3])
        : "r"(a[0]), "r"(a[1]), "r"(a[2]), "r"(a[3]),
          "r"(b[0]), "r"(b[1]));
}

__device__ __forceinline__ void ldsm_x4(u32 addr, u32& r0, u32& r1, u32& r2, u32& r3) {
    asm volatile(
        "ldmatrix.sync.aligned.m8n8.x4.shared.b16 {%0,%1,%2,%3}, [%4];"
        : "=r"(r0), "=r"(r1), "=r"(r2), "=r"(r3) : "r"(addr));
}

// Prefetch one tile's 18x18 bsa halo into smem buffer (cp.async, zfill OOB).
__device__ __forceinline__ void halo_load(int t, u32 dstbase, int tid) {
    int b = t / NP, r = t - b * NP;
    int ty0 = (r / GG) * 16 - 1, tx0 = (r - (r / GG) * GG) * 16 - 1;
    for (int idx = tid; idx < 324 * 4; idx += 256) {
        int pixel = idx >> 2, c = idx & 3;
        int hy = pixel / 18, hx = pixel - hy * 18;
        int gy = ty0 + hy, gx = tx0 + hx;
        bool ok = (gy >= 0) & (gy < HH) & (gx >= 0) & (gx < WW);
        const int8_t* src = ok
            ? g_bsa + ((size_t)((b * HH + gy) * WW + gx)) * CIN + c * 16
            : g_bsa;
        cp16(dstbase + pixel * HALO_STRIDE + c * 16, src, ok ? 16 : 0);
    }
}

__global__ void __launch_bounds__(256, 2) stage2_kernel(float* __restrict__ out) {
    extern __shared__ char sm[];
    const u32 smb = (u32)__cvta_generic_to_shared(sm);
    const int tid = threadIdx.x;
    const int mh = blockIdx.x & 1;          // fixed channel half for this block
    const int q  = blockIdx.x >> 1;         // tile start

    // Load this half's weights once (cp.async) + first halo.
    {
        const int8_t* wsrc = g_wA + (size_t)(mh * 64) * WA_STRIDE;
        for (int i = tid; i < SMEM_A_BYTES / 16; i += 256)
            cp16(smb + i * 16, wsrc + i * 16, 16);
    }
    halo_load(q, smb + SMEM_A_BYTES, tid);
    cp_commit();
    cp_wait0();
    __syncthreads();

    const int warp = tid >> 5, lane = tid & 31;
    const int wn = warp;                    // 8 N-warps
    const int gid = lane >> 2, tig = lane & 3;

    // A LDSM addresses (fixed): 4 m16 tiles over the 64 smem-resident rows.
    u32 aaddr[4];
#pragma unroll
    for (int i = 0; i < 4; i++)
        aaddr[i] = smb + (u32)((i * 16 + (lane & 15)) * WA_STRIDE
                               + ((lane >> 4) << 4));

    // B LDSM lane offsets relative to halo-buffer base.
    u32 brel[2];
    int pty[2];
#pragma unroll
    for (int jr = 0; jr < 2; jr++) {
        int ty = wn * 2 + jr;
        pty[jr] = ty;
        brel[jr] = (u32)((ty * 18 + ((lane >> 4) << 3) + (lane & 7)) * HALO_STRIDE
                         + ((lane >> 3) & 1) * 16);
    }

    int w = 0;
    for (int t = q; t < NTILES; t += 148, w++) {
        const u32 curbase = smb + SMEM_A_BYTES + (u32)((w & 1) * SMEM_HALO_BYTES);

        // Prefetch next tile's halo into the other buffer.
        if (t + 148 < NTILES)
            halo_load(t + 148, smb + SMEM_A_BYTES + (u32)(((w + 1) & 1) * SMEM_HALO_BYTES), tid);
        cp_commit();

        int acc[4][4][4];
#pragma unroll
        for (int i = 0; i < 4; i++)
#pragma unroll
            for (int j = 0; j < 4; j++)
#pragma unroll
                for (int k = 0; k < 4; k++) acc[i][j][k] = 0;

#pragma unroll
        for (int ks = 0; ks < 18; ks++) {
            const int tp = ks >> 1, h = ks & 1;
            const int dy = tp / 3, dx = tp - dy * 3;
            const u32 bofs = (u32)((dy * 18 + dx) * HALO_STRIDE + h * 32);
            const u32 aofs = (u32)(ks * 32);

            u32 a[4][4];
#pragma unroll
            for (int i = 0; i < 4; i++)
                ldsm_x4(aaddr[i] + aofs, a[i][0], a[i][1], a[i][2], a[i][3]);

            u32 bb[2][4];
#pragma unroll
            for (int jr = 0; jr < 2; jr++)
                ldsm_x4(curbase + brel[jr] + bofs, bb[jr][0], bb[jr][1], bb[jr][2], bb[jr][3]);

#pragma unroll
            for (int i = 0; i < 4; i++)
#pragma unroll
                for (int j = 0; j < 4; j++)
                    mma_s8(acc[i][j], a[i], &bb[j >> 1][(j & 1) * 2]);
        }

        // Epilogue
        {
            int b = t / NP, r = t - b * NP;
            int y0 = (r / GG) * 16, x0 = (r - (r / GG) * GG) * 16;
#pragma unroll
            for (int i = 0; i < 4; i++) {
                int o = mh * 64 + i * 16 + gid;
#pragma unroll
                for (int j = 0; j < 4; j++) {
                    int gy = y0 + pty[j >> 1];
                    int gx = x0 + (j & 1) * 8 + tig * 2;
                    size_t base0 = ((size_t)(b * COUT + o)) * HW + (size_t)gy * WW + gx;
                    *(float2*)(out + base0) =
                        make_float2((float)acc[i][j][0], (float)acc[i][j][1]);
                    *(float2*)(out + base0 + (size_t)8 * HW) =
                        make_float2((float)acc[i][j][2], (float)acc[i][j][3]);
                }
            }
        }

        // Single barrier: prefetch landed + everyone done reading curbase.
        cp_wait0();
        __syncthreads();
    }
}

// ---------------------------------------------------------------------------
// Launch
// ---------------------------------------------------------------------------
extern "C" void kernel_launch(void* const* d_in, const int* in_sizes, int n_in,
                              void* d_out, int out_size) {
    const float* x  = (const float*)d_in[0];
    const float* pf = (const float*)d_in[2];
    const float* of = (const float*)d_in[3];
    float* out = (float*)d_out;

    cudaFuncSetAttribute(stage2_kernel,
                         cudaFuncAttributeMaxDynamicSharedMemorySize, SMEM_TOTAL);

    pack_pf_kernel<<<(NP * 9 + 255) / 256, 256>>>(pf);
    pack_wA_kernel<<<(COUT * WA_STRIDE + 255) / 256, 256>>>(of);

    stage1_kernel<<<dim3(WW / 32, GG, BB), 128>>>(x);

    stage2_kernel<<<NBLK2, 256, SMEM_TOTAL>>>(out);
}

// round 11
// speedup vs baseline: 1.5116x; 1.0450x over previous
#include <cuda_runtime.h>
#include <cstdint>

// Problem constants
#define BB   8
#define CIN  64
#define COUT 128
#define HH   224
#define WW   224
#define HW   (HH * WW)
#define PTCH 16
#define GG   14     // 14x14 patch grid
#define NP   196
#define NTILES (BB * GG * GG)   // 1568
#define NBLK2 296               // persistent stage2 blocks (2 per SM)

typedef unsigned long long u64;
typedef unsigned int u32;

// ---------------------------------------------------------------------------
// Scratch (device globals — no allocations allowed)
// ---------------------------------------------------------------------------
__device__ u64 g_pw[NP * 9];                           // packed sign(patch_filters)
__device__ __align__(16) int8_t g_bsa[(size_t)BB * HW * CIN];  // ternary bsa, channels-last

#define WA_STRIDE 592                                  // 576 + pad; 20 quad-banks mod 32 -> conflict-free
__device__ __align__(16) int8_t g_wA[COUT * WA_STRIDE];  // int8 weights, row o, k = t*64+h*32+kl

// ---------------------------------------------------------------------------
// cp.async helpers
// ---------------------------------------------------------------------------
__device__ __forceinline__ void cp16(u32 dst, const void* src, int srcsize) {
    asm volatile("cp.async.cg.shared.global [%0], [%1], 16, %2;\n"
                 :: "r"(dst), "l"(src), "r"(srcsize));
}
__device__ __forceinline__ void cp_commit() { asm volatile("cp.async.commit_group;\n"); }
__device__ __forceinline__ void cp_wait0()  { asm volatile("cp.async.wait_group 0;\n"); }

// ---------------------------------------------------------------------------
// Kernel 0 (merged): pack patch-filter sign bits AND output-conv int8 rows.
// ---------------------------------------------------------------------------
__global__ void pack_kernel(const float* __restrict__ pf,
                            const float* __restrict__ of) {
    int idx = blockIdx.x * blockDim.x + threadIdx.x;
    if (idx < NP * 9) {
        int p = idx / 9, t = idx - p * 9;
        u64 w = 0;
#pragma unroll
        for (int c = 0; c < CIN; c++) {
            unsigned sb = __float_as_uint(pf[((size_t)c * NP + p) * 9 + t]) >> 31;
            w |= (u64)sb << c;
        }
        g_pw[idx] = w;
    } else if (idx < NP * 9 + COUT * WA_STRIDE) {
        int j = idx - NP * 9;
        int o = j / WA_STRIDE, kg = j - o * WA_STRIDE;
        int8_t v = 0;
        if (kg < 576) {
            int t = kg >> 6, c = kg & 63;
            unsigned sb = __float_as_uint(of[((size_t)o * CIN + c) * 9 + t]) >> 31;
            v = sb ? (int8_t)-1 : (int8_t)1;
        }
        g_wA[j] = v;
    }
}

// ---------------------------------------------------------------------------
// 32x32 bit-matrix transpose within a warp (5 shfl_xor steps).
// Input: lane r holds word with bit c = M[r][c]. Output: bit c = M[c][r].
// ---------------------------------------------------------------------------
__device__ __forceinline__ u32 bit_transpose32(u32 x, int lane) {
#pragma unroll
    for (int s = 16; s >= 1; s >>= 1) {
        u32 m;
        if      (s == 16) m = 0x0000FFFFu;
        else if (s == 8)  m = 0x00FF00FFu;
        else if (s == 4)  m = 0x0F0F0F0Fu;
        else if (s == 2)  m = 0x33333333u;
        else              m = 0x55555555u;
        u32 y = __shfl_xor_sync(0xFFFFFFFFu, x, s);
        x = (lane & s) ? ((x & ~m) | ((y >> s) & m))
                       : ((x & m) | ((y & m) << s));
    }
    return x;
}

// ---------------------------------------------------------------------------
// Kernel 1: fused sign-pack (ballot + warp bit-transpose) + per-patch
// depthwise binary 3x3 -> ternary int8 bsa.
// Block = one 16x16 patch, 256 threads = 8 warps; warp w owns rows {2w, 2w+1}.
// Sign pack: 64x (coalesced LDG + ballot) = one bit-mask per channel, then
// two 32x32 bit transposes flip channel-major masks into per-pixel u64 words.
// ---------------------------------------------------------------------------
__global__ void __launch_bounds__(256) stage1_kernel(const float* __restrict__ x) {
    __shared__ u64 tile[PTCH][PTCH];
    __shared__ u64 pw9[9];

    const int tid  = threadIdx.x;
    const int w    = tid >> 5, lane = tid & 31;
    const int r    = 2 * w + (lane >> 4);   // patch row for this lane's pixel
    const int col  = lane & 15;             // patch col
    const int gx = blockIdx.x, gy = blockIdx.y, b = blockIdx.z;

    const int y  = gy * PTCH + r;
    const int xc = gx * PTCH + col;
    const float* xp = x + (size_t)b * CIN * HW + (size_t)y * WW + xc;

    // Pack: for each channel, ballot the 32 pixels' sign bits; lane c keeps
    // channel c's mask; transpose so lane p holds its pixel's channel bits.
    u32 halfw[2];
#pragma unroll
    for (int h = 0; h < 2; h++) {
        float v[32];
#pragma unroll
        for (int cc = 0; cc < 32; cc++)
            v[cc] = xp[(size_t)(h * 32 + cc) * HW];
        u32 mym = 0;
#pragma unroll
        for (int cc = 0; cc < 32; cc++) {
            u32 bal = __ballot_sync(0xFFFFFFFFu, __float_as_int(v[cc]) < 0);
            if (lane == cc) mym = bal;
        }
        halfw[h] = bit_transpose32(mym, lane);
    }
    tile[r][col] = (u64)halfw[0] | ((u64)halfw[1] << 32);

    if (tid < 9) pw9[tid] = g_pw[(gy * GG + gx) * 9 + tid];
    __syncthreads();

    // Depthwise binary 3x3 (zero pad inside patch), ternary quantize.
    const int i = tid >> 4, j = tid & 15;

    u64 c0 = 0, c1 = 0, c2 = 0, c3 = 0;
#pragma unroll
    for (int di = 0; di < 3; di++) {
#pragma unroll
        for (int dj = 0; dj < 3; dj++) {
            int li = i + di - 1, lj = j + dj - 1;
            if (li >= 0 && li < PTCH && lj >= 0 && lj < PTCH) {
                u64 d = tile[li][lj] ^ pw9[di * 3 + dj];
                u64 carry = d, u;
                u = c0 & carry; c0 ^= carry; carry = u;
                u = c1 & carry; c1 ^= carry; carry = u;
                u = c2 & carry; c2 ^= carry; carry = u;
                c3 ^= carry;
            }
        }
    }

    const int ni = (i == 0 || i == PTCH - 1) ? 2 : 3;
    const int nj = (j == 0 || j == PTCH - 1) ? 2 : 3;
    const int n  = ni * nj;

    u64 m, s;
    if (n == 9) {
        m = ~0ULL;
        s = c3 | (c2 & (c1 | c0));
    } else if (n == 6) {
        m = ~(c0 & c1 & ~c2);
        s = c2;
    } else { // n == 4
        m = ~(c1 & ~c0 & ~c2);
        s = (c0 & c1) | c2;
    }

    // Emit ternary int8: m ? (s ? -1 : +1) : 0, channels-last.
    u32 w32[16];
#pragma unroll
    for (int wi = 0; wi < 16; wi++) {
        u32 v = 0;
#pragma unroll
        for (int bi = 0; bi < 4; bi++) {
            int c = wi * 4 + bi;
            u32 mb = (u32)((m >> c) & 1ULL);
            u32 sb = (u32)((s >> c) & 1ULL);
            u32 byte = mb ? (sb ? 0xFFu : 0x01u) : 0u;
            v |= byte << (bi * 8);
        }
        w32[wi] = v;
    }
    uint4* dst = (uint4*)(g_bsa + ((size_t)((b * HH + gy * PTCH + i) * WW
                                            + gx * PTCH + j)) * CIN);
    dst[0] = make_uint4(w32[0],  w32[1],  w32[2],  w32[3]);
    dst[1] = make_uint4(w32[4],  w32[5],  w32[6],  w32[7]);
    dst[2] = make_uint4(w32[8],  w32[9],  w32[10], w32[11]);
    dst[3] = make_uint4(w32[12], w32[13], w32[14], w32[15]);
}

// ---------------------------------------------------------------------------
// Kernel 2: PERSISTENT split-M int8 implicit GEMM (mma.sync + ldmatrix).
// (unchanged from validated R9 kernel)
// ---------------------------------------------------------------------------
#define HALO_STRIDE 80
#define SMEM_A_BYTES (64 * WA_STRIDE)            // 37888 (half the channels)
#define SMEM_HALO_BYTES (18 * 18 * HALO_STRIDE)  // 25920
#define SMEM_TOTAL (SMEM_A_BYTES + 2 * SMEM_HALO_BYTES)   // 89728

__device__ __forceinline__ void mma_s8(int* d, const u32* a, const u32* b) {
    asm volatile(
        "mma.sync.aligned.m16n8k32.row.col.s32.s8.s8.s32 "
        "{%0,%1,%2,%3}, {%4,%5,%6,%7}, {%8,%9}, {%0,%1,%2,%3};\n"
        : "+r"(d[0]), "+r"(d[1]), "+r"(d[2]), "+r"(d[3])
        : "r"(a[0]), "r"(a[1]), "r"(a[2]), "r"(a[3]),
          "r"(b[0]), "r"(b[1]));
}

__device__ __forceinline__ void ldsm_x4(u32 addr, u32& r0, u32& r1, u32& r2, u32& r3) {
    asm volatile(
        "ldmatrix.sync.aligned.m8n8.x4.shared.b16 {%0,%1,%2,%3}, [%4];"
        : "=r"(r0), "=r"(r1), "=r"(r2), "=r"(r3) : "r"(addr));
}

__device__ __forceinline__ void halo_load(int t, u32 dstbase, int tid) {
    int b = t / NP, r = t - b * NP;
    int ty0 = (r / GG) * 16 - 1, tx0 = (r - (r / GG) * GG) * 16 - 1;
    for (int idx = tid; idx < 324 * 4; idx += 256) {
        int pixel = idx >> 2, c = idx & 3;
        int hy = pixel / 18, hx = pixel - hy * 18;
        int gy = ty0 + hy, gx = tx0 + hx;
        bool ok = (gy >= 0) & (gy < HH) & (gx >= 0) & (gx < WW);
        const int8_t* src = ok
            ? g_bsa + ((size_t)((b * HH + gy) * WW + gx)) * CIN + c * 16
            : g_bsa;
        cp16(dstbase + pixel * HALO_STRIDE + c * 16, src, ok ? 16 : 0);
    }
}

__global__ void __launch_bounds__(256, 2) stage2_kernel(float* __restrict__ out) {
    extern __shared__ char sm[];
    const u32 smb = (u32)__cvta_generic_to_shared(sm);
    const int tid = threadIdx.x;
    const int mh = blockIdx.x & 1;          // fixed channel half for this block
    const int q  = blockIdx.x >> 1;         // tile start

    {
        const int8_t* wsrc = g_wA + (size_t)(mh * 64) * WA_STRIDE;
        for (int i = tid; i < SMEM_A_BYTES / 16; i += 256)
            cp16(smb + i * 16, wsrc + i * 16, 16);
    }
    halo_load(q, smb + SMEM_A_BYTES, tid);
    cp_commit();
    cp_wait0();
    __syncthreads();

    const int warp = tid >> 5, lane = tid & 31;
    const int wn = warp;                    // 8 N-warps
    const int gid = lane >> 2, tig = lane & 3;

    u32 aaddr[4];
#pragma unroll
    for (int i = 0; i < 4; i++)
        aaddr[i] = smb + (u32)((i * 16 + (lane & 15)) * WA_STRIDE
                               + ((lane >> 4) << 4));

    u32 brel[2];
    int pty[2];
#pragma unroll
    for (int jr = 0; jr < 2; jr++) {
        int ty = wn * 2 + jr;
        pty[jr] = ty;
        brel[jr] = (u32)((ty * 18 + ((lane >> 4) << 3) + (lane & 7)) * HALO_STRIDE
                         + ((lane >> 3) & 1) * 16);
    }

    int w = 0;
    for (int t = q; t < NTILES; t += 148, w++) {
        const u32 curbase = smb + SMEM_A_BYTES + (u32)((w & 1) * SMEM_HALO_BYTES);

        if (t + 148 < NTILES)
            halo_load(t + 148, smb + SMEM_A_BYTES + (u32)(((w + 1) & 1) * SMEM_HALO_BYTES), tid);
        cp_commit();

        int acc[4][4][4];
#pragma unroll
        for (int i = 0; i < 4; i++)
#pragma unroll
            for (int j = 0; j < 4; j++)
#pragma unroll
                for (int k = 0; k < 4; k++) acc[i][j][k] = 0;

#pragma unroll
        for (int ks = 0; ks < 18; ks++) {
            const int tp = ks >> 1, h = ks & 1;
            const int dy = tp / 3, dx = tp - dy * 3;
            const u32 bofs = (u32)((dy * 18 + dx) * HALO_STRIDE + h * 32);
            const u32 aofs = (u32)(ks * 32);

            u32 a[4][4];
#pragma unroll
            for (int i = 0; i < 4; i++)
                ldsm_x4(aaddr[i] + aofs, a[i][0], a[i][1], a[i][2], a[i][3]);

            u32 bb[2][4];
#pragma unroll
            for (int jr = 0; jr < 2; jr++)
                ldsm_x4(curbase + brel[jr] + bofs, bb[jr][0], bb[jr][1], bb[jr][2], bb[jr][3]);

#pragma unroll
            for (int i = 0; i < 4; i++)
#pragma unroll
                for (int j = 0; j < 4; j++)
                    mma_s8(acc[i][j], a[i], &bb[j >> 1][(j & 1) * 2]);
        }

        {
            int b = t / NP, r = t - b * NP;
            int y0 = (r / GG) * 16, x0 = (r - (r / GG) * GG) * 16;
#pragma unroll
            for (int i = 0; i < 4; i++) {
                int o = mh * 64 + i * 16 + gid;
#pragma unroll
                for (int j = 0; j < 4; j++) {
                    int gy = y0 + pty[j >> 1];
                    int gx = x0 + (j & 1) * 8 + tig * 2;
                    size_t base0 = ((size_t)(b * COUT + o)) * HW + (size_t)gy * WW + gx;
                    *(float2*)(out + base0) =
                        make_float2((float)acc[i][j][0], (float)acc[i][j][1]);
                    *(float2*)(out + base0 + (size_t)8 * HW) =
                        make_float2((float)acc[i][j][2], (float)acc[i][j][3]);
                }
            }
        }

        cp_wait0();
        __syncthreads();
    }
}

// ---------------------------------------------------------------------------
// Launch
// ---------------------------------------------------------------------------
extern "C" void kernel_launch(void* const* d_in, const int* in_sizes, int n_in,
                              void* d_out, int out_size) {
    const float* x  = (const float*)d_in[0];
    const float* pf = (const float*)d_in[2];
    const float* of = (const float*)d_in[3];
    float* out = (float*)d_out;

    cudaFuncSetAttribute(stage2_kernel,
                         cudaFuncAttributeMaxDynamicSharedMemorySize, SMEM_TOTAL);

    const int npk = NP * 9 + COUT * WA_STRIDE;
    pack_kernel<<<(npk + 255) / 256, 256>>>(pf, of);

    stage1_kernel<<<dim3(GG, GG, BB), 256>>>(x);

    stage2_kernel<<<NBLK2, 256, SMEM_TOTAL>>>(out);
}